// round 4
// baseline (speedup 1.0000x reference)
#include <cuda_runtime.h>
#include <math.h>

#define B 32
#define T 1024
#define NIN 64
#define NRES 2048
#define NOUT 64
#define CAP 288            // padded pairs per row (blocks of 8; nnz ~205+6sd)
#define NBMAX (CAP / 8)    // 36 blocks max
#define SCAN_CTAS 128
#define RPC 64             // rows per CTA (32 row-groups)
#define BCAP 96            // per-residue bucket capacity in build (51 mean, 6.4sd)

// Layout for U and S: idx(t, bg, n, j) = (((t*4)+bg)*NRES + n)*8 + j,  b = bg*8+j
// Static device scratch (sanctioned by harness rules).
__device__ uint2 g_pairs[NRES][CAP];                      // {w_bits, byte_off=k*32} ~4.7 MB
__device__ int   g_cnt[NRES];                             // blocks of 8 per row
__device__ float g_U[(size_t)T * NRES * B];               // 256 MB
__device__ float g_S[(size_t)(T + 1) * NRES * B];         // 256 MB, t=0 slice = 0
__device__ unsigned long long g_bar4[4 * 16];             // 4 counters, 128 B apart

// ---------------------------------------------------------------------------
__global__ void init_kernel() {
    int tid = blockIdx.x * blockDim.x + threadIdx.x;
    if (tid < 4) g_bar4[tid * 16] = 0ULL;
    for (int i = tid; i < NRES * B; i += gridDim.x * blockDim.x)
        g_S[i] = 0.f;
}

// ---------------------------------------------------------------------------
// Build residue-scheduled ELL: bucket nnz by k&3, emit blocks of 8 where even
// positions have distinct residues and odd positions have distinct residues
// (-> conflict-free smem gather octets). Greedy fallback when buckets drain.
// ---------------------------------------------------------------------------
__global__ __launch_bounds__(256) void build_sparse_kernel(const float* __restrict__ W_res) {
    __shared__ uint2 s_buck[8][4][BCAP];
    int warp = threadIdx.x >> 5;
    int lane = threadIdx.x & 31;
    int n = blockIdx.x * 8 + warp;
    if (n >= NRES) return;
    const float* row = W_res + (size_t)n * NRES;

    int c0 = 0, c1 = 0, c2 = 0, c3 = 0;
    int myres = lane & 3;
    unsigned mymask = 0x11111111u << myres;
    for (int c = 0; c < NRES; c += 32) {
        float w = row[c + lane];
        int k = c + lane;                    // k&3 == lane&3 (c % 4 == 0)
        bool nz = (w != 0.f);
        unsigned bz = __ballot_sync(0xffffffffu, nz);
        if (nz) {
            int base = (myres == 0) ? c0 : (myres == 1) ? c1 : (myres == 2) ? c2 : c3;
            int off = base + __popc(bz & mymask & ((1u << lane) - 1u));
            if (off < BCAP)
                s_buck[warp][myres][off] = make_uint2(__float_as_uint(w), (unsigned)(k * 32));
        }
        c0 += __popc(bz & 0x11111111u);
        c1 += __popc(bz & 0x22222222u);
        c2 += __popc(bz & 0x44444444u);
        c3 += __popc(bz & 0x88888888u);
    }
    __syncwarp();
    if (lane == 0) {
        int cs[4] = { c0 < BCAP ? c0 : BCAP, c1 < BCAP ? c1 : BCAP,
                      c2 < BCAP ? c2 : BCAP, c3 < BCAP ? c3 : BCAP };
        int total = cs[0] + cs[1] + cs[2] + cs[3];
        int nb = (total + 7) / 8;
        if (nb > NBMAX) nb = NBMAX;
        if (nb < 1) nb = 1;
        int rp[4] = {0, 0, 0, 0};
        const int prefE[4] = {0, 1, 2, 3};
        const int prefO[4] = {2, 3, 0, 1};
        for (int p = 0; p < nb * 8; p++) {
            int g = (p >> 1) & 3;
            int want = (p & 1) ? prefO[g] : prefE[g];
            int sel = -1;
            if (rp[want] < cs[want]) sel = want;
            else {
                int best = -1, bc = 0;
                for (int r = 0; r < 4; r++) {
                    int rem = cs[r] - rp[r];
                    if (rem > bc) { bc = rem; best = r; }
                }
                sel = best;   // -1 if all empty
            }
            uint2 e;
            if (sel >= 0) e = s_buck[warp][sel][rp[sel]++];
            else          e = make_uint2(0u, (unsigned)(want * 32));
            g_pairs[n][p] = e;
        }
        g_cnt[n] = nb;
    }
}

// ---------------------------------------------------------------------------
// U[t][n][b] = b_res[n] + sum_d x[b][t][d] * W_in[n][d]  (bg-blocked layout)
// ---------------------------------------------------------------------------
__global__ __launch_bounds__(256) void u_kernel(const float* __restrict__ x,
                                                const float* __restrict__ W_in,
                                                const float* __restrict__ b_res) {
    __shared__ float s_w[64 * 68];
    __shared__ float s_x[64 * 33];
    int tid = threadIdx.x;
    int n0 = blockIdx.x * 64;
    int t0 = blockIdx.y * 16;

    for (int i = tid; i < 64 * 64; i += 256) {
        int nl = i >> 6, d = i & 63;
        s_w[d * 68 + nl] = W_in[(size_t)(n0 + nl) * NIN + d];
    }

    int warp = tid >> 5, lane = tid & 31;
    int bgl = lane >> 3, bl = lane & 7;
    float bias[8];
#pragma unroll
    for (int i = 0; i < 8; i++) bias[i] = __ldg(b_res + n0 + warp * 8 + i);

    for (int tt = 0; tt < 16; tt++) {
        int t = t0 + tt;
        __syncthreads();
        for (int i = tid; i < B * 64; i += 256) {
            int b = i >> 6, d = i & 63;
            s_x[d * 33 + b] = x[((size_t)b * T + t) * NIN + d];
        }
        __syncthreads();

        float acc[8];
#pragma unroll
        for (int i = 0; i < 8; i++) acc[i] = 0.f;
#pragma unroll 4
        for (int d = 0; d < 64; d++) {
            float xv = s_x[d * 33 + lane];
            float4 w0 = *(const float4*)&s_w[d * 68 + warp * 8];
            float4 w1 = *(const float4*)&s_w[d * 68 + warp * 8 + 4];
            acc[0] = fmaf(w0.x, xv, acc[0]);
            acc[1] = fmaf(w0.y, xv, acc[1]);
            acc[2] = fmaf(w0.z, xv, acc[2]);
            acc[3] = fmaf(w0.w, xv, acc[3]);
            acc[4] = fmaf(w1.x, xv, acc[4]);
            acc[5] = fmaf(w1.y, xv, acc[5]);
            acc[6] = fmaf(w1.z, xv, acc[6]);
            acc[7] = fmaf(w1.w, xv, acc[7]);
        }
        size_t ub = ((size_t)t * 4 + bgl) * NRES;
#pragma unroll
        for (int i = 0; i < 8; i++) {
            int n = n0 + warp * 8 + i;
            g_U[(ub + n) * 8 + bl] = acc[i] + bias[i];
        }
    }
}

// ---------------------------------------------------------------------------
// Persistent scan: 128 CTAs = 32 row-groups x 4 batch-groups, 1024 threads.
// Per step: bulk-load this bg's h slice (64 KB, contiguous) into smem, then
// gather from smem (conflict-scheduled LDS), 2 rows per warp, 4 nnz-groups x
// 8 batch lanes. Per-bg 32-CTA barriers (groups are independent).
// ---------------------------------------------------------------------------
__global__ __launch_bounds__(1024, 1) void scan_kernel() {
    extern __shared__ float smem[];
    float* s_h = smem;                                   // 2048*8 floats, 64 KB
    char*  s_pairs = (char*)(smem + NRES * 8);           // RPC*CAP*8 = 144 KB
    int*   s_cnt = (int*)(s_pairs + (size_t)RPC * CAP * 8);

    int tid  = threadIdx.x;
    int warp = tid >> 5;          // 0..31
    int lane = tid & 31;
    int rg   = blockIdx.x >> 2;
    int bg   = blockIdx.x & 3;
    int n0   = rg * RPC;

    // prologue: stage pairs + counts (rows n0..n0+63 contiguous in g_pairs)
    {
        const uint4* gp = (const uint4*)&g_pairs[n0][0];
        uint4* sp4 = (uint4*)s_pairs;
        for (int i = tid; i < RPC * CAP / 2; i += 1024) sp4[i] = gp[i];
        if (tid < RPC) s_cnt[tid] = g_cnt[n0 + tid];
    }
    __syncthreads();

    const int g  = lane >> 3;        // nnz subgroup 0..3
    const int b4 = (lane & 7) * 4;   // batch byte offset within row
    const int r0 = warp * 2;         // two rows per warp
    const uint4* pp0 = (const uint4*)(s_pairs + (size_t)r0 * CAP * 8);
    const uint4* pp1 = (const uint4*)(s_pairs + (size_t)(r0 + 1) * CAP * 8);
    const int nb0 = s_cnt[r0], nb1 = s_cnt[r0 + 1];
    volatile unsigned long long* bar = &g_bar4[bg * 16];

    for (int t = 0; t < T; t++) {
        size_t hblock = ((size_t)t * 4 + bg) * NRES * 8;
        size_t oblock = ((size_t)(t + 1) * 4 + bg) * NRES * 8;

        // bulk load h slice into smem (contiguous 64 KB)
        {
            const float4* src = (const float4*)(g_S + hblock);
            float4* dst = (float4*)s_h;
#pragma unroll
            for (int i = 0; i < 4; i++) dst[tid + i * 1024] = src[tid + i * 1024];
        }
        // preload u for both rows (lanes 0-7 -> row0, 8-15 -> row1)
        float uval = 0.f;
        if (lane < 16) {
            int ur = n0 + r0 + (lane >> 3);
            uval = g_U[hblock + (size_t)ur * 8 + (lane & 7)];
        }
        __syncthreads();   // h slice ready

#pragma unroll
        for (int rr = 0; rr < 2; rr++) {
            const uint4* pp = rr ? pp1 : pp0;
            const int nb = rr ? nb1 : nb0;
            float acc0 = 0.f, acc1 = 0.f;
#pragma unroll 4
            for (int jb = 0; jb < nb; jb++) {
                uint4 pk = pp[jb * 4 + g];
                float h0 = *(const float*)((const char*)s_h + pk.y + b4);
                float h1 = *(const float*)((const char*)s_h + pk.w + b4);
                acc0 = fmaf(__uint_as_float(pk.x), h0, acc0);
                acc1 = fmaf(__uint_as_float(pk.z), h1, acc1);
            }
            float acc = acc0 + acc1;
#pragma unroll
            for (int ofs = 8; ofs <= 16; ofs <<= 1)
                acc += __shfl_xor_sync(0xffffffffu, acc, ofs);
            float u = rr ? __shfl_sync(0xffffffffu, uval, lane + 8) : uval;
            if (lane < 8) {
                int n = n0 + r0 + rr;
                g_S[oblock + (size_t)n * 8 + lane] = tanhf(u + acc);
            }
        }

        // ---- per-bg grid barrier (32 CTAs, monotonic counter) ----
        __syncthreads();
        if (tid == 0) {
            __threadfence();
            atomicAdd((unsigned long long*)bar, 1ULL);
            unsigned long long target = (unsigned long long)(t + 1) * 32;
            while (*bar < target) { }
            __threadfence();
        }
        __syncthreads();
    }
}

// ---------------------------------------------------------------------------
// y[b][t][o] = b_out[o] + sum_n S[t+1][bg(b)][n][b&7] * W_out[o][n]
// ---------------------------------------------------------------------------
__global__ __launch_bounds__(256) void readout_kernel(const float* __restrict__ W_out,
                                                      const float* __restrict__ b_out,
                                                      float* __restrict__ y) {
    __shared__ float s_wo[128 * 68];
    int tid = threadIdx.x, warp = tid >> 5, lane = tid & 31;
    int t = blockIdx.x;
    int bgl = lane >> 3, bl = lane & 7;

    float acc[8];
#pragma unroll
    for (int i = 0; i < 8; i++) acc[i] = 0.f;

    const float* sp = g_S + ((size_t)(t + 1) * 4 + bgl) * NRES * 8 + bl;

    for (int ch = 0; ch < NRES / 128; ch++) {
        __syncthreads();
        for (int i = tid; i < 128 * 64; i += 256) {
            int nl = i & 127, o = i >> 7;
            s_wo[nl * 68 + o] = W_out[(size_t)o * NRES + ch * 128 + nl];
        }
        __syncthreads();
#pragma unroll 4
        for (int nl = 0; nl < 128; nl++) {
            float sv = __ldg(sp + (size_t)(ch * 128 + nl) * 8);
            float4 w0 = *(const float4*)&s_wo[nl * 68 + warp * 8];
            float4 w1 = *(const float4*)&s_wo[nl * 68 + warp * 8 + 4];
            acc[0] = fmaf(w0.x, sv, acc[0]);
            acc[1] = fmaf(w0.y, sv, acc[1]);
            acc[2] = fmaf(w0.z, sv, acc[2]);
            acc[3] = fmaf(w0.w, sv, acc[3]);
            acc[4] = fmaf(w1.x, sv, acc[4]);
            acc[5] = fmaf(w1.y, sv, acc[5]);
            acc[6] = fmaf(w1.z, sv, acc[6]);
            acc[7] = fmaf(w1.w, sv, acc[7]);
        }
    }
#pragma unroll
    for (int i = 0; i < 8; i++) {
        int o = warp * 8 + i;
        y[((size_t)lane * T + t) * NOUT + o] = acc[i] + __ldg(b_out + o);
    }
}

// ---------------------------------------------------------------------------
extern "C" void kernel_launch(void* const* d_in, const int* in_sizes, int n_in,
                              void* d_out, int out_size) {
    const float* x     = (const float*)d_in[0];
    const float* W_in  = (const float*)d_in[1];
    const float* W_res = (const float*)d_in[2];
    const float* b_res = (const float*)d_in[3];
    const float* W_out = (const float*)d_in[4];
    const float* b_out = (const float*)d_in[5];
    float* y = (float*)d_out;

    const int SMEM_SCAN = NRES * 8 * 4 + RPC * CAP * 8 + RPC * 4;  // 213248 B
    cudaFuncSetAttribute(scan_kernel, cudaFuncAttributeMaxDynamicSharedMemorySize, SMEM_SCAN);

    init_kernel<<<64, 256>>>();
    build_sparse_kernel<<<NRES / 8, 256>>>(W_res);
    dim3 gu(NRES / 64, T / 16);
    u_kernel<<<gu, 256>>>(x, W_in, b_res);
    scan_kernel<<<SCAN_CTAS, 1024, SMEM_SCAN>>>();
    readout_kernel<<<T, 256>>>(W_out, b_out, y);
}

// round 5
// speedup vs baseline: 1.2358x; 1.2358x over previous
#include <cuda_runtime.h>
#include <math.h>

#define B 32
#define T 1024
#define NIN 64
#define NRES 2048
#define NOUT 64
#define CAP 320            // max padded nnz per row (mean 204.8, sd 13.6)
#define SCAN_CTAS 128
#define ROWS_PER_CTA 16    // 128 * 16 = 2048, one row per warp (512 thr/CTA)

struct __align__(8) Pair { float w; int k; };

// Static device scratch (sanctioned by harness rules).
__device__ Pair  g_pairs[NRES][CAP];                      // ~5.2 MB
__device__ int   g_cnt[NRES];
__device__ float g_U[(size_t)T * NRES * B];               // 256 MB: [t][n][b]
__device__ float g_S[(size_t)(T + 1) * NRES * B];         // 256 MB: [t][n][b], g_S[0]=0
__device__ unsigned long long g_bar;

// ---------------------------------------------------------------------------
// Init: zero h_0 and the barrier counter (runs every launch/replay).
// ---------------------------------------------------------------------------
__global__ void init_kernel() {
    int tid = blockIdx.x * blockDim.x + threadIdx.x;
    if (tid == 0) g_bar = 0ULL;
    for (int i = tid; i < NRES * B; i += gridDim.x * blockDim.x)
        g_S[i] = 0.f;
}

// ---------------------------------------------------------------------------
// Build sparse ELL of W_res: one warp per row, k-ascending deterministic order.
// Pads each row's nnz to a multiple of 16 with zero-weight entries.
// ---------------------------------------------------------------------------
__global__ void build_sparse_kernel(const float* __restrict__ W_res) {
    int warp = threadIdx.x >> 5;
    int lane = threadIdx.x & 31;
    int n = blockIdx.x * 8 + warp;            // grid 256 x 256 threads
    if (n >= NRES) return;
    const float* row = W_res + (size_t)n * NRES;
    int base = 0;
    for (int c = 0; c < NRES; c += 32) {
        float w = row[c + lane];
        unsigned mask = __ballot_sync(0xffffffffu, w != 0.f);
        int pos = base + __popc(mask & ((1u << lane) - 1u));
        if (w != 0.f && pos < CAP) {
            g_pairs[n][pos].w = w;
            g_pairs[n][pos].k = c + lane;
        }
        base += __popc(mask);
    }
    if (lane == 0) {
        int cnt = base < CAP ? base : CAP;
        int cnt16 = (cnt + 15) & ~15;          // pad to multiple of 16
        if (cnt16 > CAP) cnt16 = CAP;
        g_cnt[n] = cnt16;
        for (int j = cnt; j < cnt16; j++) {
            g_pairs[n][j].w = 0.f;
            g_pairs[n][j].k = 0;
        }
    }
}

// ---------------------------------------------------------------------------
// U[t][n][b] = b_res[n] + sum_d x[b][t][d] * W_in[n][d]
// ---------------------------------------------------------------------------
__global__ __launch_bounds__(256) void u_kernel(const float* __restrict__ x,
                                                const float* __restrict__ W_in,
                                                const float* __restrict__ b_res) {
    __shared__ float s_w[64 * 68];   // [d][n_l], stride 68
    __shared__ float s_x[64 * 33];   // [d][b],  stride 33
    int tid = threadIdx.x;
    int n0 = blockIdx.x * 64;
    int t0 = blockIdx.y * 16;

    for (int i = tid; i < 64 * 64; i += 256) {
        int nl = i >> 6, d = i & 63;
        s_w[d * 68 + nl] = W_in[(size_t)(n0 + nl) * NIN + d];
    }

    int warp = tid >> 5, lane = tid & 31;
    float bias[8];
#pragma unroll
    for (int i = 0; i < 8; i++) bias[i] = __ldg(b_res + n0 + warp * 8 + i);

    for (int tt = 0; tt < 16; tt++) {
        int t = t0 + tt;
        __syncthreads();
        for (int i = tid; i < B * 64; i += 256) {
            int b = i >> 6, d = i & 63;
            s_x[d * 33 + b] = x[((size_t)b * T + t) * NIN + d];
        }
        __syncthreads();

        float acc[8];
#pragma unroll
        for (int i = 0; i < 8; i++) acc[i] = 0.f;
#pragma unroll 4
        for (int d = 0; d < 64; d++) {
            float xv = s_x[d * 33 + lane];
            float4 w0 = *(const float4*)&s_w[d * 68 + warp * 8];
            float4 w1 = *(const float4*)&s_w[d * 68 + warp * 8 + 4];
            acc[0] = fmaf(w0.x, xv, acc[0]);
            acc[1] = fmaf(w0.y, xv, acc[1]);
            acc[2] = fmaf(w0.z, xv, acc[2]);
            acc[3] = fmaf(w0.w, xv, acc[3]);
            acc[4] = fmaf(w1.x, xv, acc[4]);
            acc[5] = fmaf(w1.y, xv, acc[5]);
            acc[6] = fmaf(w1.z, xv, acc[6]);
            acc[7] = fmaf(w1.w, xv, acc[7]);
        }
        float* out = g_U + ((size_t)t * NRES + n0 + warp * 8) * B + lane;
#pragma unroll
        for (int i = 0; i < 8; i++) out[(size_t)i * B] = acc[i] + bias[i];
    }
}

// ---------------------------------------------------------------------------
// Persistent scan: 128 CTAs x 512 threads, ONE ROW PER WARP, vectorized gather
// (round-2 compute config). New: release/acquire grid barrier (no membar.gpu)
// and next-step U prefetch hidden under the barrier wait.
// ---------------------------------------------------------------------------
__global__ __launch_bounds__(512, 1) void scan_kernel() {
    __shared__ Pair s_pairs[ROWS_PER_CTA][CAP];   // 40 KB
    __shared__ int  s_cnt[ROWS_PER_CTA];
    int tid  = threadIdx.x;
    int warp = tid >> 5;          // 0..15  = row within CTA
    int lane = tid & 31;
    int n0   = blockIdx.x * ROWS_PER_CTA;
    int n    = n0 + warp;

    // each warp stages its own row's (padded) pairs
    {
        int cnt = g_cnt[n];
        if (lane == 0) s_cnt[warp] = cnt;
        for (int j = lane; j < cnt; j += 32)
            s_pairs[warp][j] = g_pairs[n][j];
    }
    __syncthreads();

    const int g  = lane >> 3;        // nnz subgroup 0..3
    const int bq = (lane & 7) * 4;   // batch quad offset
    const Pair* __restrict__ pp = s_pairs[warp];
    const int cnt = s_cnt[warp];

    // prefetch u for t=0 (only lanes with g==0 consume it)
    float4 u = make_float4(0.f, 0.f, 0.f, 0.f);
    if (g == 0) u = *(const float4*)(g_U + (size_t)n * B + bq);

    for (int t = 0; t < T; t++) {
        const float* __restrict__ hp = g_S + (size_t)t * NRES * B;
        float*       __restrict__ hn = g_S + (size_t)(t + 1) * NRES * B;

        float4 acc = make_float4(0.f, 0.f, 0.f, 0.f);
#pragma unroll 4
        for (int j = 0; j < cnt; j += 4) {
            Pair p = pp[j + g];                                  // LDS.64, bcast in group
            float4 h = __ldg((const float4*)(hp + (size_t)p.k * B + bq));
            acc.x = fmaf(p.w, h.x, acc.x);
            acc.y = fmaf(p.w, h.y, acc.y);
            acc.z = fmaf(p.w, h.z, acc.z);
            acc.w = fmaf(p.w, h.w, acc.w);
        }
        // reduce the 4 nnz groups (xor 8, 16)
#pragma unroll
        for (int ofs = 8; ofs <= 16; ofs <<= 1) {
            acc.x += __shfl_xor_sync(0xffffffffu, acc.x, ofs);
            acc.y += __shfl_xor_sync(0xffffffffu, acc.y, ofs);
            acc.z += __shfl_xor_sync(0xffffffffu, acc.z, ofs);
            acc.w += __shfl_xor_sync(0xffffffffu, acc.w, ofs);
        }
        if (g == 0) {
            float4 hv;
            hv.x = tanhf(u.x + acc.x);
            hv.y = tanhf(u.y + acc.y);
            hv.z = tanhf(u.z + acc.z);
            hv.w = tanhf(u.w + acc.w);
            *(float4*)(hn + (size_t)n * B + bq) = hv;
        }

        // ---- grid barrier: syncthreads + release-add, acquire-poll ----
        __syncthreads();                           // all CTA stores done
        if (tid == 0) {
            // release: makes this CTA's h stores visible to acquirers
            asm volatile("red.release.gpu.global.add.u64 [%0], %1;"
                         :: "l"(&g_bar), "l"(1ULL) : "memory");
        }
        // prefetch next step's u while we wait (independent of the barrier)
        float4 u_next = make_float4(0.f, 0.f, 0.f, 0.f);
        if (g == 0 && t + 1 < T)
            u_next = *(const float4*)(g_U + ((size_t)(t + 1) * NRES + n) * B + bq);
        if (tid == 0) {
            unsigned long long target = (unsigned long long)(t + 1) * SCAN_CTAS;
            unsigned long long cur;
            do {
                asm volatile("ld.acquire.gpu.global.u64 %0, [%1];"
                             : "=l"(cur) : "l"(&g_bar) : "memory");
            } while (cur < target);
        }
        __syncthreads();                           // broadcast the acquire
        u = u_next;
    }
}

// ---------------------------------------------------------------------------
// y[b][t][o] = b_out[o] + sum_n S[t+1][n][b] * W_out[o][n]
// ---------------------------------------------------------------------------
__global__ __launch_bounds__(256) void readout_kernel(const float* __restrict__ W_out,
                                                      const float* __restrict__ b_out,
                                                      float* __restrict__ y) {
    __shared__ float s_wo[128 * 68];   // [n_l][o], stride 68
    int tid = threadIdx.x, warp = tid >> 5, lane = tid & 31;
    int t = blockIdx.x;

    float acc[8];
#pragma unroll
    for (int i = 0; i < 8; i++) acc[i] = 0.f;

    const float* sp_base = g_S + (size_t)(t + 1) * NRES * B;

    for (int ch = 0; ch < NRES / 128; ch++) {
        __syncthreads();
        for (int i = tid; i < 128 * 64; i += 256) {
            int nl = i & 127, o = i >> 7;
            s_wo[nl * 68 + o] = W_out[(size_t)o * NRES + ch * 128 + nl];
        }
        __syncthreads();
        const float* sp = sp_base + (size_t)ch * 128 * B;
#pragma unroll 4
        for (int nl = 0; nl < 128; nl++) {
            float sv = __ldg(sp + nl * B + lane);
            float4 w0 = *(const float4*)&s_wo[nl * 68 + warp * 8];
            float4 w1 = *(const float4*)&s_wo[nl * 68 + warp * 8 + 4];
            acc[0] = fmaf(w0.x, sv, acc[0]);
            acc[1] = fmaf(w0.y, sv, acc[1]);
            acc[2] = fmaf(w0.z, sv, acc[2]);
            acc[3] = fmaf(w0.w, sv, acc[3]);
            acc[4] = fmaf(w1.x, sv, acc[4]);
            acc[5] = fmaf(w1.y, sv, acc[5]);
            acc[6] = fmaf(w1.z, sv, acc[6]);
            acc[7] = fmaf(w1.w, sv, acc[7]);
        }
    }
#pragma unroll
    for (int i = 0; i < 8; i++) {
        int o = warp * 8 + i;
        y[((size_t)lane * T + t) * NOUT + o] = acc[i] + __ldg(b_out + o);
    }
}

// ---------------------------------------------------------------------------
extern "C" void kernel_launch(void* const* d_in, const int* in_sizes, int n_in,
                              void* d_out, int out_size) {
    const float* x     = (const float*)d_in[0];  // [32,1024,64]
    const float* W_in  = (const float*)d_in[1];  // [2048,64]
    const float* W_res = (const float*)d_in[2];  // [2048,2048]
    const float* b_res = (const float*)d_in[3];  // [2048]
    const float* W_out = (const float*)d_in[4];  // [64,2048]
    const float* b_out = (const float*)d_in[5];  // [64]
    float* y = (float*)d_out;                    // [32,1024,64]

    init_kernel<<<64, 256>>>();
    build_sparse_kernel<<<NRES / 8, 256>>>(W_res);
    dim3 gu(NRES / 64, T / 16);
    u_kernel<<<gu, 256>>>(x, W_in, b_res);
    scan_kernel<<<SCAN_CTAS, 512>>>();
    readout_kernel<<<T, 256>>>(W_out, b_out, y);
}